// round 1
// baseline (speedup 1.0000x reference)
#include <cuda_runtime.h>
#include <math.h>

#define B_  4
#define N_  1024
#define DM  512
#define NH  8
#define DH  64
#define SCALE 0.17677669529663687f   // (dh/2)^-0.5 = 1/sqrt(32)

// Scratch (allocation-free rule: device globals)
__device__ float g_Q [B_*NH*N_*DH];   // rotated Q, (b,h,n,d)
__device__ float g_K [B_*NH*N_*DH];   // rotated K, (b,h,n,d)
__device__ float g_V [B_*NH*N_*DH];   // V, (b,h,n,d)
__device__ float g_AO[B_*N_*DM];      // attention out, (b,n,h*dh)

// ---------------------------------------------------------------------------
// Kernel 1: fused QKV GEMM (shared X tile, 3 weight tiles) + RoPE epilogue.
// Tiles: BM=64, BN=64, BK=16; 256 threads; 4x4 micro-tile per thread per output.
// ---------------------------------------------------------------------------
__global__ __launch_bounds__(256) void qkv_rot_kernel(
    const float* __restrict__ x,  const float* __restrict__ Wq,
    const float* __restrict__ Wk, const float* __restrict__ Wv,
    const float* __restrict__ pos, const float* __restrict__ fr)
{
    __shared__ float Xs[16][68];            // [k][m], padded (272B stride, 16B aligned)
    __shared__ float Wqs[16][64], Wks[16][64], Wvs[16][64];
    const int t = threadIdx.x;
    const int row0 = blockIdx.y * 64, col0 = blockIdx.x * 64;
    const int tx = t & 15, ty = t >> 4;
    const int lxm = t >> 2,  lxk = (t & 3) << 2;   // X loader: row lxm, 4 consecutive k
    const int lwk = t >> 4,  lwc = (t & 15) << 2;  // W loader: k row lwk, 4 cols

    float aq[4][4] = {}, ak[4][4] = {}, av[4][4] = {};

    for (int k0 = 0; k0 < DM; k0 += 16) {
        float4 xv = *(const float4*)(x + (size_t)(row0+lxm)*DM + k0 + lxk);
        Xs[lxk+0][lxm] = xv.x; Xs[lxk+1][lxm] = xv.y;
        Xs[lxk+2][lxm] = xv.z; Xs[lxk+3][lxm] = xv.w;
        *(float4*)&Wqs[lwk][lwc] = *(const float4*)(Wq + (size_t)(k0+lwk)*DM + col0 + lwc);
        *(float4*)&Wks[lwk][lwc] = *(const float4*)(Wk + (size_t)(k0+lwk)*DM + col0 + lwc);
        *(float4*)&Wvs[lwk][lwc] = *(const float4*)(Wv + (size_t)(k0+lwk)*DM + col0 + lwc);
        __syncthreads();
#pragma unroll
        for (int k = 0; k < 16; k++) {
            float4 xf = *(const float4*)&Xs [k][ty<<2];
            float4 qf = *(const float4*)&Wqs[k][tx<<2];
            float4 kf = *(const float4*)&Wks[k][tx<<2];
            float4 vf = *(const float4*)&Wvs[k][tx<<2];
            float xa[4] = {xf.x, xf.y, xf.z, xf.w};
            float qa[4] = {qf.x, qf.y, qf.z, qf.w};
            float ka[4] = {kf.x, kf.y, kf.z, kf.w};
            float va[4] = {vf.x, vf.y, vf.z, vf.w};
#pragma unroll
            for (int i = 0; i < 4; i++)
#pragma unroll
                for (int j = 0; j < 4; j++) {
                    aq[i][j] += xa[i]*qa[j];
                    ak[i][j] += xa[i]*ka[j];
                    av[i][j] += xa[i]*va[j];
                }
        }
        __syncthreads();
    }

    // Epilogue: per-head layout + rotation of (even, odd) channel pairs.
    // Tile is 64 cols wide and 64-aligned -> single head per CTA column tile.
    const int h  = col0 >> 6;
    const int d0 = tx << 2;          // 4 contiguous channels = 2 rotation pairs
#pragma unroll
    for (int i = 0; i < 4; i++) {
        const int r = row0 + (ty<<2) + i;
        const int b = r >> 10, n = r & (N_-1);
        const size_t base = ((size_t)(b*NH+h)*N_ + n)*DH;
#pragma unroll
        for (int j = 0; j < 4; j++) g_V[base + d0 + j] = av[i][j];
        const float p0 = pos[2*n], p1 = pos[2*n+1];
#pragma unroll
        for (int p = 0; p < 2; p++) {
            const int m = (d0 >> 1) + p;         // channel pair index
            const float ang = p0*fr[(h*32+m)*2] + p1*fr[(h*32+m)*2+1];
            float sn, cs; sincosf(ang, &sn, &cs);
            const float qe = aq[i][2*p], qo = aq[i][2*p+1];
            const float ke = ak[i][2*p], ko = ak[i][2*p+1];
            g_Q[base + d0 + 2*p    ] = qe*cs - qo*sn;
            g_Q[base + d0 + 2*p + 1] = qe*sn + qo*cs;
            g_K[base + d0 + 2*p    ] = ke*cs - ko*sn;
            g_K[base + d0 + 2*p + 1] = ke*sn + ko*cs;
        }
    }
}

// ---------------------------------------------------------------------------
// Kernel 2: flash attention, fp32. CTA = (b,h, 64-row tile). 256 threads.
// Smem: Qs/Ks [d][r|c] transposed, Vs/Ps natural/transposed, all stride 68.
// ---------------------------------------------------------------------------
__global__ __launch_bounds__(256) void attn_kernel()
{
    extern __shared__ float sm[];
    float* Qs = sm;               // [64][68]  [d][r]
    float* Ks = sm + 64*68;       // [64][68]  [d][c]
    float* Vs = sm + 2*64*68;     // [64][68]  [j][c]
    float* Ps = sm + 3*64*68;     // [64][68]  [j][r]

    const int t = threadIdx.x, tx = t & 15, ty = t >> 4;
    const int bh = blockIdx.y, rt = blockIdx.x;
    const float* Qb = g_Q + ((size_t)bh*N_ + rt*64)*DH;
    const float* Kb = g_K + (size_t)bh*N_*DH;
    const float* Vb = g_V + (size_t)bh*N_*DH;
    const int lr = t >> 2, ld0 = (t & 3) << 4;   // loader: row lr, 16 elems at ld0

#pragma unroll
    for (int q = 0; q < 4; q++) {
        float4 v = *(const float4*)(Qb + lr*DH + ld0 + q*4);
        const int d = ld0 + q*4;
        Qs[(d+0)*68+lr]=v.x; Qs[(d+1)*68+lr]=v.y;
        Qs[(d+2)*68+lr]=v.z; Qs[(d+3)*68+lr]=v.w;
    }

    float mi[4], li[4], acc[4][4];
#pragma unroll
    for (int i = 0; i < 4; i++) {
        mi[i] = -1e30f; li[i] = 0.f;
#pragma unroll
        for (int j = 0; j < 4; j++) acc[i][j] = 0.f;
    }

    for (int jt = 0; jt < 16; jt++) {
        const float* Kt = Kb + (size_t)jt*64*DH;
        const float* Vt = Vb + (size_t)jt*64*DH;
#pragma unroll
        for (int q = 0; q < 4; q++) {
            const int d = ld0 + q*4;
            float4 kv = *(const float4*)(Kt + lr*DH + d);
            Ks[(d+0)*68+lr]=kv.x; Ks[(d+1)*68+lr]=kv.y;
            Ks[(d+2)*68+lr]=kv.z; Ks[(d+3)*68+lr]=kv.w;
            *(float4*)(Vs + lr*68 + d) = *(const float4*)(Vt + lr*DH + d);
        }
        __syncthreads();   // (A) tiles + (iter 0) Qs visible

        float s[4][4];
#pragma unroll
        for (int i = 0; i < 4; i++)
#pragma unroll
            for (int j = 0; j < 4; j++) s[i][j] = 0.f;
#pragma unroll 16
        for (int k = 0; k < 64; k++) {
            float4 qf = *(const float4*)(Qs + k*68 + (ty<<2));
            float4 kf = *(const float4*)(Ks + k*68 + (tx<<2));
            float qa[4] = {qf.x, qf.y, qf.z, qf.w};
            float ka[4] = {kf.x, kf.y, kf.z, kf.w};
#pragma unroll
            for (int i = 0; i < 4; i++)
#pragma unroll
                for (int j = 0; j < 4; j++) s[i][j] += qa[i]*ka[j];
        }

        // online softmax; row r = ty*4+i is shared by the 16 tx-lanes (shfl group)
#pragma unroll
        for (int i = 0; i < 4; i++) {
#pragma unroll
            for (int j = 0; j < 4; j++) s[i][j] *= SCALE;
            float mx = fmaxf(fmaxf(s[i][0], s[i][1]), fmaxf(s[i][2], s[i][3]));
#pragma unroll
            for (int o = 1; o < 16; o <<= 1)
                mx = fmaxf(mx, __shfl_xor_sync(0xffffffffu, mx, o));
            const float mn = fmaxf(mi[i], mx);
            const float al = __expf(mi[i] - mn);
            float rs = 0.f;
#pragma unroll
            for (int j = 0; j < 4; j++) {
                const float pv = __expf(s[i][j] - mn);
                Ps[((tx<<2)+j)*68 + (ty<<2)+i] = pv;
                rs += pv;
            }
#pragma unroll
            for (int o = 1; o < 16; o <<= 1)
                rs += __shfl_xor_sync(0xffffffffu, rs, o);
            li[i] = li[i]*al + rs;
            mi[i] = mn;
#pragma unroll
            for (int j = 0; j < 4; j++) acc[i][j] *= al;
        }
        __syncthreads();   // (B) Ps visible; Ks reads done

#pragma unroll 16
        for (int k = 0; k < 64; k++) {
            float4 pf = *(const float4*)(Ps + k*68 + (ty<<2));
            float4 vf = *(const float4*)(Vs + k*68 + (tx<<2));
            float pa[4] = {pf.x, pf.y, pf.z, pf.w};
            float va[4] = {vf.x, vf.y, vf.z, vf.w};
#pragma unroll
            for (int i = 0; i < 4; i++)
#pragma unroll
                for (int j = 0; j < 4; j++) acc[i][j] += pa[i]*va[j];
        }
        __syncthreads();   // (C) Vs/Ps reads done before next tile load
    }

    const int b = bh >> 3, h = bh & 7;
#pragma unroll
    for (int i = 0; i < 4; i++) {
        const float inv = 1.0f / li[i];
        const int n = rt*64 + (ty<<2) + i;
        const size_t o = ((size_t)b*N_ + n)*DM + h*64 + (tx<<2);
#pragma unroll
        for (int j = 0; j < 4; j++) g_AO[o + j] = acc[i][j]*inv;
    }
}

// ---------------------------------------------------------------------------
// Kernel 3: output GEMM: out = AO (4096x512) @ W_O (512x512)
// ---------------------------------------------------------------------------
__global__ __launch_bounds__(256) void out_gemm_kernel(
    const float* __restrict__ Wo, float* __restrict__ out)
{
    __shared__ float As[16][68];
    __shared__ float Bs[16][64];
    const int t = threadIdx.x;
    const int row0 = blockIdx.y * 64, col0 = blockIdx.x * 64;
    const int tx = t & 15, ty = t >> 4;
    const int lxm = t >> 2,  lxk = (t & 3) << 2;
    const int lwk = t >> 4,  lwc = (t & 15) << 2;
    float acc[4][4] = {};

    for (int k0 = 0; k0 < DM; k0 += 16) {
        float4 av = *(const float4*)(g_AO + (size_t)(row0+lxm)*DM + k0 + lxk);
        As[lxk+0][lxm] = av.x; As[lxk+1][lxm] = av.y;
        As[lxk+2][lxm] = av.z; As[lxk+3][lxm] = av.w;
        *(float4*)&Bs[lwk][lwc] = *(const float4*)(Wo + (size_t)(k0+lwk)*DM + col0 + lwc);
        __syncthreads();
#pragma unroll
        for (int k = 0; k < 16; k++) {
            float4 af = *(const float4*)&As[k][ty<<2];
            float4 bf = *(const float4*)&Bs[k][tx<<2];
            float aa[4] = {af.x, af.y, af.z, af.w};
            float ba[4] = {bf.x, bf.y, bf.z, bf.w};
#pragma unroll
            for (int i = 0; i < 4; i++)
#pragma unroll
                for (int j = 0; j < 4; j++) acc[i][j] += aa[i]*ba[j];
        }
        __syncthreads();
    }
#pragma unroll
    for (int i = 0; i < 4; i++)
#pragma unroll
        for (int j = 0; j < 4; j++)
            out[(size_t)(row0+(ty<<2)+i)*DM + col0 + (tx<<2) + j] = acc[i][j];
}

// ---------------------------------------------------------------------------
extern "C" void kernel_launch(void* const* d_in, const int* in_sizes, int n_in,
                              void* d_out, int out_size)
{
    const float* x   = (const float*)d_in[0];
    const float* pos = (const float*)d_in[1];
    const float* Wq  = (const float*)d_in[2];
    const float* Wk  = (const float*)d_in[3];
    const float* Wv  = (const float*)d_in[4];
    const float* Wo  = (const float*)d_in[5];
    // d_in[6] = U: unused. QR(U) is square full-rank -> P = Uq Uq^T = I (fp32 roundoff).
    const float* fr  = (const float*)d_in[7];

    const int attn_smem = 4*64*68*4;   // 69632 B dynamic smem
    cudaFuncSetAttribute(attn_kernel, cudaFuncAttributeMaxDynamicSharedMemorySize, attn_smem);

    qkv_rot_kernel<<<dim3(8, 64), 256>>>(x, Wq, Wk, Wv, pos, fr);
    attn_kernel<<<dim3(16, 32), 256, attn_smem>>>();
    out_gemm_kernel<<<dim3(8, 64), 256>>>(Wo, (float*)d_out);
}